// round 7
// baseline (speedup 1.0000x reference)
#include <cuda_runtime.h>
#include <cstdint>

// Problem constants (fixed by the reference).
#define BB 32
#define TT 4096
#define DD 128
#define CHUNK 16
#define CC (TT / CHUNK)        // 256 chunks per batch
#define HB 16                  // batches per half-pass
#define CH_HALF (HB * CC)      // 4096 chunks per half
#define NAGG (BB * CC * DD)    // 1M aggregate slots (full problem)

// Scratch (static device memory — no allocations).
// fwd: (last_x, last_t, has, -) per chunk; bwd: (first_x, first_t, has, -)
__device__ float4 g_fwd[NAGG];            // 16 MB
__device__ float4 g_bwd[NAGG];            // 16 MB
__device__ float2 g_pre[NAGG];            // 8 MB, incoming fwd state (defaults folded)
__device__ float2 g_suf[NAGG];            // 8 MB, incoming bwd state (defaults folded)
// Packed mask: 4 words per (b, timestep). Word k, bit l  <->  channel d = 4*l + k.
__device__ unsigned g_mw[BB * TT * 4];    // 2 MB

// ---------------------------------------------------------------------------
// Phase 1: warp-per-chunk, lane handles 4 channels via float4/int4.
// Produces per-chunk fwd/bwd aggregates + packed mask bits. b0 = batch offset.
// ---------------------------------------------------------------------------
__global__ __launch_bounds__(128) void phase1(const float4* __restrict__ v,
                                              const float4* __restrict__ t,
                                              const int4* __restrict__ m,
                                              int b0) {
    int wid = threadIdx.x >> 5, lane = threadIdx.x & 31;
    int lloc = blockIdx.x * 4 + wid;           // chunk id within half
    int b = b0 + lloc / CC, c = lloc % CC;
    int row0 = b * TT + c * CHUNK;             // first timestep of chunk
    int base4 = row0 * (DD / 4) + lane;        // float4 index

    float lx0=0.f,lx1=0.f,lx2=0.f,lx3=0.f, lt0=0.f,lt1=0.f,lt2=0.f,lt3=0.f;
    float fx0=0.f,fx1=0.f,fx2=0.f,fx3=0.f, ft0=0.f,ft1=0.f,ft2=0.f,ft3=0.f;
    bool h0=false,h1=false,h2=false,h3=false;

#pragma unroll 4
    for (int i = 0; i < CHUNK; i++) {
        float4 v4 = v[base4 + i * (DD / 4)];
        float4 t4 = t[base4 + i * (DD / 4)];
        int4   m4 = m[base4 + i * (DD / 4)];
        bool b0m = (m4.x != 0), b1m = (m4.y != 0), b2m = (m4.z != 0), b3m = (m4.w != 0);
        unsigned w0 = __ballot_sync(0xffffffffu, b0m);
        unsigned w1 = __ballot_sync(0xffffffffu, b1m);
        unsigned w2 = __ballot_sync(0xffffffffu, b2m);
        unsigned w3 = __ballot_sync(0xffffffffu, b3m);
        unsigned ws = (lane == 0) ? w0 : (lane == 1) ? w1 : (lane == 2) ? w2 : w3;
        if (lane < 4) g_mw[(row0 + i) * 4 + lane] = ws;

        if (b0m) { if (!h0) { fx0 = v4.x; ft0 = t4.x; } lx0 = v4.x; lt0 = t4.x; h0 = true; }
        if (b1m) { if (!h1) { fx1 = v4.y; ft1 = t4.y; } lx1 = v4.y; lt1 = t4.y; h1 = true; }
        if (b2m) { if (!h2) { fx2 = v4.z; ft2 = t4.z; } lx2 = v4.z; lt2 = t4.z; h2 = true; }
        if (b3m) { if (!h3) { fx3 = v4.w; ft3 = t4.w; } lx3 = v4.w; lt3 = t4.w; h3 = true; }
    }

    int o = (b * CC + c) * DD + 4 * lane;
    g_fwd[o + 0] = make_float4(lx0, lt0, h0 ? 1.f : 0.f, 0.f);
    g_fwd[o + 1] = make_float4(lx1, lt1, h1 ? 1.f : 0.f, 0.f);
    g_fwd[o + 2] = make_float4(lx2, lt2, h2 ? 1.f : 0.f, 0.f);
    g_fwd[o + 3] = make_float4(lx3, lt3, h3 ? 1.f : 0.f, 0.f);
    g_bwd[o + 0] = make_float4(fx0, ft0, h0 ? 1.f : 0.f, 0.f);
    g_bwd[o + 1] = make_float4(fx1, ft1, h1 ? 1.f : 0.f, 0.f);
    g_bwd[o + 2] = make_float4(fx2, ft2, h2 ? 1.f : 0.f, 0.f);
    g_bwd[o + 3] = make_float4(fx3, ft3, h3 ? 1.f : 0.f, 0.f);
}

// ---------------------------------------------------------------------------
// Phase 2: cross-chunk exclusive scans, warp-parallel.
// One warp per (batch, channel, direction). Each lane folds 8 chunk
// aggregates (combine = right if right.has else left), 5-step shfl_up
// inclusive scan, shift to exclusive, fold default seed (x=0, t=t0/t_max),
// then replay writing exclusive per-chunk states.
// ---------------------------------------------------------------------------
__global__ __launch_bounds__(256) void phase2(const float* __restrict__ t, int b0) {
    int gw = (blockIdx.x * blockDim.x + threadIdx.x) >> 5;   // warp id within half
    int lane = threadIdx.x & 31;
    int dir = gw & 1;
    int pair = gw >> 1;                 // [0, HB*DD)
    int b = b0 + pair / DD, d = pair % DD;

    const float4* agg = dir ? g_bwd : g_fwd;
    float2* outp      = dir ? g_suf : g_pre;
    float seed_t = dir ? t[(b * TT + TT - 1) * DD + d]       // t_max (cumsum, dt>0)
                       : t[(b * TT) * DD + d];               // t0

    // Load this lane's 8 aggregates along the scan direction.
    float4 a[8];
    int cbase = lane * 8;
#pragma unroll
    for (int j = 0; j < 8; j++) {
        int rc = cbase + j;
        int c = dir ? (CC - 1 - rc) : rc;
        a[j] = agg[(b * CC + c) * DD + d];
    }

    // Lane-local inclusive aggregate.
    float x = 0.f, tc = 0.f; int h = 0;
#pragma unroll
    for (int j = 0; j < 8; j++)
        if (a[j].z != 0.f) { x = a[j].x; tc = a[j].y; h = 1; }

    // Warp inclusive scan.
#pragma unroll
    for (int off = 1; off < 32; off <<= 1) {
        float px = __shfl_up_sync(0xffffffffu, x, off);
        float pt = __shfl_up_sync(0xffffffffu, tc, off);
        int   ph = __shfl_up_sync(0xffffffffu, h, off);
        if (lane >= off && !h) { x = px; tc = pt; h = ph; }
    }

    // Exclusive = shift by 1; fold default seed where nothing observed yet.
    float ex = __shfl_up_sync(0xffffffffu, x, 1);
    float et = __shfl_up_sync(0xffffffffu, tc, 1);
    int   eh = __shfl_up_sync(0xffffffffu, h, 1);
    if (lane == 0 || !eh) { ex = 0.f; et = seed_t; }

    // Replay: write exclusive state per chunk, then fold that chunk in.
    float sx = ex, st = et;
#pragma unroll
    for (int j = 0; j < 8; j++) {
        int rc = cbase + j;
        int c = dir ? (CC - 1 - rc) : rc;
        outp[(b * CC + c) * DD + d] = make_float2(sx, st);
        if (a[j].z != 0.f) { sx = a[j].x; st = a[j].y; }
    }
}

// ---------------------------------------------------------------------------
// Phase 3: local rescan + interpolation. 256-thread block = 2 chunks (one per
// 128-thread group). Fill state in registers (16-deep arrays), mask bits from
// the packed words. Re-reads of v,t hit L2 (half-batch working set resident).
// Blocks walk chunks in reverse of phase 1's read order for maximal L2 reuse;
// output uses streaming stores to avoid evicting hot lines.
// ---------------------------------------------------------------------------
__global__ __launch_bounds__(256) void phase3(const float* __restrict__ v,
                                              const float* __restrict__ t,
                                              float* __restrict__ out,
                                              int b0) {
    int grp = threadIdx.x >> 7;
    int d = threadIdx.x & 127;
    int lloc = (CH_HALF - 1) - (blockIdx.x * 2 + grp);  // reverse order
    int b = b0 + lloc / CC, c = lloc % CC;
    int row0 = b * TT + c * CHUNK;
    int base = row0 * DD + d;
    int o = (b * CC + c) * DD + d;
    int wsel = (d & 3), bsel = (d >> 2);

    float2 pre = g_pre[o];
    float xl = pre.x, tl = pre.y;
    float fxl[CHUNK], ftl[CHUNK];
    unsigned mbits = 0;

#pragma unroll
    for (int i = 0; i < CHUNK; i++) {
        float vv = v[base + i * DD];
        float tt = t[base + i * DD];
        unsigned w = g_mw[(row0 + i) * 4 + wsel];
        bool mm = (w >> bsel) & 1u;
        mbits |= (mm ? (1u << i) : 0u);
        if (mm) { xl = vv; tl = tt; }
        fxl[i] = xl; ftl[i] = tl;
    }

    float2 suf = g_suf[o];
    float xn = suf.x, tn = suf.y;

#pragma unroll
    for (int i = CHUNK - 1; i >= 0; i--) {
        float vv = v[base + i * DD];           // L1/L2 hit
        float tt = t[base + i * DD];           // L1/L2 hit
        bool mm = (mbits >> i) & 1u;
        if (mm) { xn = vv; tn = tt; }
        float denom = tn - ftl[i];
        float num = fmaf(fxl[i], tn - tt, xn * (tt - ftl[i]));
        float itp = (denom != 0.f) ? (num / denom) : 0.f;
        float res = mm ? vv : itp;
        __stcs(&out[base + i * DD], res);
    }
}

// ---------------------------------------------------------------------------
extern "C" void kernel_launch(void* const* d_in, const int* in_sizes, int n_in,
                              void* d_out, int out_size) {
    const float4* v4 = (const float4*)d_in[0];
    const float4* t4 = (const float4*)d_in[1];
    const int4*   m4 = (const int4*)d_in[2];
    const float*  v  = (const float*)d_in[0];
    const float*  t  = (const float*)d_in[1];
    float* out = (float*)d_out;

    for (int h = 0; h < BB / HB; h++) {
        int b0 = h * HB;
        phase1<<<CH_HALF / 4, 128>>>(v4, t4, m4, b0);
        phase2<<<(2 * HB * DD * 32) / 256, 256>>>(t, b0);
        phase3<<<CH_HALF / 2, 256>>>(v, t, out, b0);
    }
}

// round 8
// speedup vs baseline: 1.4096x; 1.4096x over previous
#include <cuda_runtime.h>
#include <cstdint>

// Problem constants (fixed by the reference).
#define BB 32
#define TT 4096
#define DD 128
#define CHUNK 32
#define CC (TT / CHUNK)        // 128 chunks per batch
#define NCH (BB * CC)          // 4096 chunks
#define NAGG (NCH * DD)        // 524288 (chunk, channel) slots

// Scratch (static device memory — no allocations).
__device__ float4 g_fwd[NAGG];             // per-chunk last-obs (x, t, has, -)   8 MB
__device__ float4 g_bwd[NAGG];             // per-chunk first-obs (x, t, has, -)  8 MB
__device__ float2 g_pre[NAGG];             // incoming fwd state (defaults folded) 4 MB
__device__ float2 g_suf[NAGG];             // incoming bwd state (defaults folded) 4 MB
__device__ uchar4 g_head4[NCH * 32];       // head length per (chunk, quad)       0.5 MB
__device__ uchar4 g_tail4[NCH * 32];       // tail length per (chunk, quad)       0.5 MB

// ---------------------------------------------------------------------------
// Pass A: fused aggregate + local interpolation. One block = one chunk
// (32 rows x 128 channels). Vectorized staging into swizzled SMEM, then
// row-per-lane warp scans on byte-packed observation indices (vmaxs4/vmins4).
// Writes final output for all rows bracketed by in-chunk observations;
// head/tail rows (no obs before / after within chunk) get 0 and are fixed by
// pass C. Emits per-chunk aggregates and head/tail lengths.
// ---------------------------------------------------------------------------
__global__ __launch_bounds__(256) void passA(const float4* __restrict__ v,
                                             const float4* __restrict__ t,
                                             const int4* __restrict__ m,
                                             float4* __restrict__ out) {
    __shared__ float4 sv[1024];   // 16 KB  (32 rows x 32 quads, xor-swizzled)
    __shared__ float4 st[1024];   // 16 KB
    __shared__ uchar4 sm4[1024];  //  4 KB

    int chunk = blockIdx.x;
    int tid = threadIdx.x;
    int gbase = chunk * 1024;     // 32 rows * 32 float4/row

    // ---- stage in (coalesced, streaming) ----
#pragma unroll
    for (int k = 0; k < 4; k++) {
        int f = tid + k * 256;
        int row = f >> 5, q = f & 31;
        int sidx = (row << 5) | (q ^ row);
        float4 vv = __ldcs(v + gbase + f);
        float4 tt = __ldcs(t + gbase + f);
        int4   mm = __ldcs(m + gbase + f);
        sv[sidx] = vv;
        st[sidx] = tt;
        sm4[sidx] = make_uchar4(mm.x != 0, mm.y != 0, mm.z != 0, mm.w != 0);
    }
    __syncthreads();

    int lane = tid & 31, w = tid >> 5;
    float4 outq[4];

#pragma unroll
    for (int j = 0; j < 4; j++) {
        int q = w * 4 + j;                      // quad = channels 4q..4q+3
        int sidx = (lane << 5) | (q ^ lane);    // row = lane
        float4 v4 = sv[sidx];
        float4 t4 = st[sidx];
        uchar4 mb = sm4[sidx];

        // Byte-packed per-channel observation indices.
        int pf = ((mb.x ? lane : 0xFF)      ) | ((mb.y ? lane : 0xFF) <<  8) |
                 ((mb.z ? lane : 0xFF) << 16) | ((mb.w ? lane : 0xFF) << 24);
        int pb = ((mb.x ? lane : 32)        ) | ((mb.y ? lane : 32)   <<  8) |
                 ((mb.z ? lane : 32)   << 16) | ((mb.w ? lane : 32)   << 24);

        // Inclusive max-scan (last obs <= row) and reverse min-scan (first obs >= row).
#pragma unroll
        for (int off = 1; off < 32; off <<= 1) {
            int sf = __shfl_up_sync(0xffffffffu, pf, off);
            if (lane >= off) pf = __vmaxs4(pf, sf);
            int sb = __shfl_down_sync(0xffffffffu, pb, off);
            if (lane < 32 - off) pb = __vmins4(pb, sb);
        }

        float oc[4];
        float vj_a[4] = {v4.x, v4.y, v4.z, v4.w};
        float tj_a[4] = {t4.x, t4.y, t4.z, t4.w};
        unsigned char mm_a[4] = {mb.x, mb.y, mb.z, mb.w};
        int ni_a[4], li_a[4];
        float xl_a[4], tl_a[4], xn_a[4], tn_a[4];

#pragma unroll
        for (int ch = 0; ch < 4; ch++) {
            int li = (pf << (24 - 8 * ch)) >> 24;   // signed byte: last obs idx or -1
            int ni = (pb << (24 - 8 * ch)) >> 24;   // first obs idx or 32
            li_a[ch] = li; ni_a[ch] = ni;
            float vj = vj_a[ch], tj = tj_a[ch];
            float xl = __shfl_sync(0xffffffffu, vj, li & 31);
            float tl = __shfl_sync(0xffffffffu, tj, li & 31);
            float xn = __shfl_sync(0xffffffffu, vj, ni & 31);
            float tn = __shfl_sync(0xffffffffu, tj, ni & 31);
            xl_a[ch] = xl; tl_a[ch] = tl; xn_a[ch] = xn; tn_a[ch] = tn;
            float o;
            if (mm_a[ch]) o = vj;
            else if (li >= 0 && ni < 32)            // times strictly increasing -> denom > 0
                o = fmaf(xl, tn - tj, xn * (tj - tl)) / (tn - tl);
            else o = 0.f;                            // head/tail: fixed by pass C
            oc[ch] = o;
        }
        outq[j] = make_float4(oc[0], oc[1], oc[2], oc[3]);

        // Aggregates + head/tail lengths.
        if (lane == 31) {
            int o0 = chunk * DD + q * 4;
#pragma unroll
            for (int ch = 0; ch < 4; ch++)
                g_fwd[o0 + ch] = make_float4(xl_a[ch], tl_a[ch],
                                             li_a[ch] >= 0 ? 1.f : 0.f, 0.f);
            g_tail4[chunk * 32 + q] = make_uchar4(
                li_a[0] < 0 ? 0 : 31 - li_a[0], li_a[1] < 0 ? 0 : 31 - li_a[1],
                li_a[2] < 0 ? 0 : 31 - li_a[2], li_a[3] < 0 ? 0 : 31 - li_a[3]);
        }
        if (lane == 0) {
            int o0 = chunk * DD + q * 4;
#pragma unroll
            for (int ch = 0; ch < 4; ch++)
                g_bwd[o0 + ch] = make_float4(xn_a[ch], tn_a[ch],
                                             ni_a[ch] < 32 ? 1.f : 0.f, 0.f);
            g_head4[chunk * 32 + q] = make_uchar4(ni_a[0], ni_a[1], ni_a[2], ni_a[3]);
        }
    }

    // ---- stage out (reuse sv), coalesced streaming stores ----
    __syncthreads();
#pragma unroll
    for (int j = 0; j < 4; j++) {
        int q = w * 4 + j;
        sv[(lane << 5) | (q ^ lane)] = outq[j];
    }
    __syncthreads();
#pragma unroll
    for (int k = 0; k < 4; k++) {
        int f = tid + k * 256;
        int row = f >> 5, q = f & 31;
        __stcs(out + gbase + f, sv[(row << 5) | (q ^ row)]);
    }
}

// ---------------------------------------------------------------------------
// Pass B: cross-chunk exclusive scans, warp-parallel. One warp per
// (batch, channel, direction); lane folds 4 chunk aggregates, shfl_up scan
// (combine = right if right.has else left), shift to exclusive, fold default
// seed (x=0, t=t0 / t_max), replay writing exclusive per-chunk states.
// ---------------------------------------------------------------------------
__global__ __launch_bounds__(256) void passB(const float* __restrict__ t) {
    int gw = (blockIdx.x * blockDim.x + threadIdx.x) >> 5;
    int lane = threadIdx.x & 31;
    int dir = gw & 1;
    int pair = gw >> 1;                 // [0, BB*DD)
    int b = pair / DD, d = pair % DD;

    const float4* agg = dir ? g_bwd : g_fwd;
    float2* outp      = dir ? g_suf : g_pre;
    float seed_t = dir ? t[(b * TT + TT - 1) * DD + d]   // t_max (cumsum, dt>0)
                       : t[(b * TT) * DD + d];           // t0

    float4 a[4];
    int cbase = lane * 4;
#pragma unroll
    for (int j = 0; j < 4; j++) {
        int rc = cbase + j;
        int c = dir ? (CC - 1 - rc) : rc;
        a[j] = agg[(b * CC + c) * DD + d];
    }

    float x = 0.f, tc = 0.f; int h = 0;
#pragma unroll
    for (int j = 0; j < 4; j++)
        if (a[j].z != 0.f) { x = a[j].x; tc = a[j].y; h = 1; }

#pragma unroll
    for (int off = 1; off < 32; off <<= 1) {
        float px = __shfl_up_sync(0xffffffffu, x, off);
        float pt = __shfl_up_sync(0xffffffffu, tc, off);
        int   ph = __shfl_up_sync(0xffffffffu, h, off);
        if (lane >= off && !h) { x = px; tc = pt; h = ph; }
    }

    float ex = __shfl_up_sync(0xffffffffu, x, 1);
    float et = __shfl_up_sync(0xffffffffu, tc, 1);
    int   eh = __shfl_up_sync(0xffffffffu, h, 1);
    if (lane == 0 || !eh) { ex = 0.f; et = seed_t; }

    float sx = ex, stt = et;
#pragma unroll
    for (int j = 0; j < 4; j++) {
        int rc = cbase + j;
        int c = dir ? (CC - 1 - rc) : rc;
        outp[(b * CC + c) * DD + d] = make_float2(sx, stt);
        if (a[j].z != 0.f) { sx = a[j].x; stt = a[j].y; }
    }
}

// ---------------------------------------------------------------------------
// Pass C: fixup of head/tail rows. One thread per (chunk, channel); repairs
// the rows with no in-chunk observation on one side using the incoming
// states + in-chunk aggregates, re-reading only t for those rows.
// ---------------------------------------------------------------------------
__global__ __launch_bounds__(256) void passC(const float* __restrict__ t,
                                             float* __restrict__ out) {
    int id = blockIdx.x * 256 + threadIdx.x;   // [0, NCH*DD)
    int chunk = id >> 7, d = id & 127;
    int row0 = chunk * CHUNK;                  // global row (CC*CHUNK == TT)

    const unsigned char* gh = (const unsigned char*)g_head4;
    const unsigned char* gt = (const unsigned char*)g_tail4;
    int head = gh[id];
    int tail = gt[id];

    if (head > 0) {
        float2 pre = g_pre[id];
        float4 bw  = g_bwd[id];
        float xn, tn;
        if (bw.z != 0.f) { xn = bw.x; tn = bw.y; }
        else { float2 sf = g_suf[id]; xn = sf.x; tn = sf.y; }
        float xl = pre.x, tl = pre.y;
        float denom = tn - tl;
        float inv = (denom != 0.f) ? (1.f / denom) : 0.f;
        for (int i = 0; i < head; i++) {
            float tt = t[(row0 + i) * DD + d];
            out[(row0 + i) * DD + d] = fmaf(xl, tn - tt, xn * (tt - tl)) * inv;
        }
    }
    if (tail > 0) {
        float4 fw = g_fwd[id];
        float2 sf = g_suf[id];
        float xl = fw.x, tl = fw.y;
        float xn = sf.x, tn = sf.y;
        float denom = tn - tl;
        float inv = (denom != 0.f) ? (1.f / denom) : 0.f;
        for (int i = CHUNK - tail; i < CHUNK; i++) {
            float tt = t[(row0 + i) * DD + d];
            out[(row0 + i) * DD + d] = fmaf(xl, tn - tt, xn * (tt - tl)) * inv;
        }
    }
}

// ---------------------------------------------------------------------------
extern "C" void kernel_launch(void* const* d_in, const int* in_sizes, int n_in,
                              void* d_out, int out_size) {
    const float4* v4 = (const float4*)d_in[0];
    const float4* t4 = (const float4*)d_in[1];
    const int4*   m4 = (const int4*)d_in[2];
    const float*  t  = (const float*)d_in[1];
    float4* out4 = (float4*)d_out;
    float*  out  = (float*)d_out;

    passA<<<NCH, 256>>>(v4, t4, m4, out4);
    passB<<<(2 * BB * DD * 32) / 256, 256>>>(t);
    passC<<<(NCH * DD) / 256, 256>>>(t, out);
}

// round 9
// speedup vs baseline: 1.4314x; 1.0155x over previous
#include <cuda_runtime.h>
#include <cstdint>

// Problem constants (fixed by the reference).
#define BB 32
#define TT 4096
#define DD 128
#define CHUNK 32
#define CC (TT / CHUNK)        // 128 chunks per batch
#define NCH (BB * CC)          // 4096 chunks
#define NAGG (NCH * DD)        // 524288 (chunk, channel) slots

// Scratch (static device memory — no allocations).
__device__ float4 g_fwd[NAGG];             // per-chunk last-obs (x, t, has, -)   8 MB
__device__ float4 g_bwd[NAGG];             // per-chunk first-obs (x, t, has, -)  8 MB
__device__ float2 g_pre[NAGG];             // incoming fwd state (defaults folded) 4 MB
__device__ float2 g_suf[NAGG];             // incoming bwd state (defaults folded) 4 MB
__device__ uchar4 g_head4[NCH * 32];       // head length per (chunk, quad)       0.5 MB
__device__ uchar4 g_tail4[NCH * 32];       // tail length per (chunk, quad)       0.5 MB

// ---------------------------------------------------------------------------
// Pass A: fused aggregate + local interpolation. One block = one chunk
// (32 rows x 128 channels). Vectorized staging into swizzled SMEM, then
// row-per-lane warp scans on byte-packed observation indices (vmaxs4/vmins4).
// Division via __fdividef (MUFU.RCP; ~2^-21 rel err, tolerance is 1e-3).
// Writes final output for all rows bracketed by in-chunk observations;
// head/tail rows are fixed by pass C. Emits aggregates + head/tail lengths.
// ---------------------------------------------------------------------------
__global__ __launch_bounds__(256) void passA(const float4* __restrict__ v,
                                             const float4* __restrict__ t,
                                             const int4* __restrict__ m,
                                             float4* __restrict__ out) {
    __shared__ float4 sv[1024];   // 16 KB  (32 rows x 32 quads, xor-swizzled)
    __shared__ float4 st[1024];   // 16 KB
    __shared__ uchar4 sm4[1024];  //  4 KB

    int chunk = blockIdx.x;
    int tid = threadIdx.x;
    int gbase = chunk * 1024;     // 32 rows * 32 float4/row

    // ---- stage in (coalesced, streaming) ----
#pragma unroll
    for (int k = 0; k < 4; k++) {
        int f = tid + k * 256;
        int row = f >> 5, q = f & 31;
        int sidx = (row << 5) | (q ^ row);
        float4 vv = __ldcs(v + gbase + f);
        float4 tt = __ldcs(t + gbase + f);
        int4   mm = __ldcs(m + gbase + f);
        sv[sidx] = vv;
        st[sidx] = tt;
        sm4[sidx] = make_uchar4(mm.x != 0, mm.y != 0, mm.z != 0, mm.w != 0);
    }
    __syncthreads();

    int lane = tid & 31, w = tid >> 5;
    float4 outq[4];

#pragma unroll
    for (int j = 0; j < 4; j++) {
        int q = w * 4 + j;                      // quad = channels 4q..4q+3
        int sidx = (lane << 5) | (q ^ lane);    // row = lane
        float4 v4 = sv[sidx];
        float4 t4 = st[sidx];
        uchar4 mb = sm4[sidx];

        // Byte-packed per-channel observation indices.
        int pf = ((mb.x ? lane : 0xFF)      ) | ((mb.y ? lane : 0xFF) <<  8) |
                 ((mb.z ? lane : 0xFF) << 16) | ((mb.w ? lane : 0xFF) << 24);
        int pb = ((mb.x ? lane : 32)        ) | ((mb.y ? lane : 32)   <<  8) |
                 ((mb.z ? lane : 32)   << 16) | ((mb.w ? lane : 32)   << 24);

        // Inclusive max-scan (last obs <= row) and reverse min-scan (first obs >= row).
#pragma unroll
        for (int off = 1; off < 32; off <<= 1) {
            int sf = __shfl_up_sync(0xffffffffu, pf, off);
            if (lane >= off) pf = __vmaxs4(pf, sf);
            int sb = __shfl_down_sync(0xffffffffu, pb, off);
            if (lane < 32 - off) pb = __vmins4(pb, sb);
        }

        float oc[4];
        float vj_a[4] = {v4.x, v4.y, v4.z, v4.w};
        float tj_a[4] = {t4.x, t4.y, t4.z, t4.w};
        unsigned char mm_a[4] = {mb.x, mb.y, mb.z, mb.w};
        int ni_a[4], li_a[4];
        float xl_a[4], tl_a[4], xn_a[4], tn_a[4];

#pragma unroll
        for (int ch = 0; ch < 4; ch++) {
            int li = (pf << (24 - 8 * ch)) >> 24;   // signed byte: last obs idx or -1
            int ni = (pb << (24 - 8 * ch)) >> 24;   // first obs idx or 32
            li_a[ch] = li; ni_a[ch] = ni;
            float vj = vj_a[ch], tj = tj_a[ch];
            float xl = __shfl_sync(0xffffffffu, vj, li & 31);
            float tl = __shfl_sync(0xffffffffu, tj, li & 31);
            float xn = __shfl_sync(0xffffffffu, vj, ni & 31);
            float tn = __shfl_sync(0xffffffffu, tj, ni & 31);
            xl_a[ch] = xl; tl_a[ch] = tl; xn_a[ch] = xn; tn_a[ch] = tn;
            float o;
            if (mm_a[ch]) o = vj;
            else if (li >= 0 && ni < 32)            // times strictly increasing -> denom > 0
                o = __fdividef(fmaf(xl, tn - tj, xn * (tj - tl)), tn - tl);
            else o = 0.f;                            // head/tail: fixed by pass C
            oc[ch] = o;
        }
        outq[j] = make_float4(oc[0], oc[1], oc[2], oc[3]);

        // Aggregates + head/tail lengths.
        if (lane == 31) {
            int o0 = chunk * DD + q * 4;
#pragma unroll
            for (int ch = 0; ch < 4; ch++)
                g_fwd[o0 + ch] = make_float4(xl_a[ch], tl_a[ch],
                                             li_a[ch] >= 0 ? 1.f : 0.f, 0.f);
            g_tail4[chunk * 32 + q] = make_uchar4(
                li_a[0] < 0 ? 0 : 31 - li_a[0], li_a[1] < 0 ? 0 : 31 - li_a[1],
                li_a[2] < 0 ? 0 : 31 - li_a[2], li_a[3] < 0 ? 0 : 31 - li_a[3]);
        }
        if (lane == 0) {
            int o0 = chunk * DD + q * 4;
#pragma unroll
            for (int ch = 0; ch < 4; ch++)
                g_bwd[o0 + ch] = make_float4(xn_a[ch], tn_a[ch],
                                             ni_a[ch] < 32 ? 1.f : 0.f, 0.f);
            g_head4[chunk * 32 + q] = make_uchar4(ni_a[0], ni_a[1], ni_a[2], ni_a[3]);
        }
    }

    // ---- stage out (reuse sv), coalesced streaming stores ----
    __syncthreads();
#pragma unroll
    for (int j = 0; j < 4; j++) {
        int q = w * 4 + j;
        sv[(lane << 5) | (q ^ lane)] = outq[j];
    }
    __syncthreads();
#pragma unroll
    for (int k = 0; k < 4; k++) {
        int f = tid + k * 256;
        int row = f >> 5, q = f & 31;
        __stcs(out + gbase + f, sv[(row << 5) | (q ^ row)]);
    }
}

// ---------------------------------------------------------------------------
// Pass B: cross-chunk exclusive scans, warp-parallel. One warp per
// (batch, channel, direction); lane folds 4 chunk aggregates, shfl_up scan
// (combine = right if right.has else left), shift to exclusive, fold default
// seed (x=0, t=t0 / t_max), replay writing exclusive per-chunk states.
// ---------------------------------------------------------------------------
__global__ __launch_bounds__(256) void passB(const float* __restrict__ t) {
    int gw = (blockIdx.x * blockDim.x + threadIdx.x) >> 5;
    int lane = threadIdx.x & 31;
    int dir = gw & 1;
    int pair = gw >> 1;                 // [0, BB*DD)
    int b = pair / DD, d = pair % DD;

    const float4* agg = dir ? g_bwd : g_fwd;
    float2* outp      = dir ? g_suf : g_pre;
    float seed_t = dir ? t[(b * TT + TT - 1) * DD + d]   // t_max (cumsum, dt>0)
                       : t[(b * TT) * DD + d];           // t0

    float4 a[4];
    int cbase = lane * 4;
#pragma unroll
    for (int j = 0; j < 4; j++) {
        int rc = cbase + j;
        int c = dir ? (CC - 1 - rc) : rc;
        a[j] = agg[(b * CC + c) * DD + d];
    }

    float x = 0.f, tc = 0.f; int h = 0;
#pragma unroll
    for (int j = 0; j < 4; j++)
        if (a[j].z != 0.f) { x = a[j].x; tc = a[j].y; h = 1; }

#pragma unroll
    for (int off = 1; off < 32; off <<= 1) {
        float px = __shfl_up_sync(0xffffffffu, x, off);
        float pt = __shfl_up_sync(0xffffffffu, tc, off);
        int   ph = __shfl_up_sync(0xffffffffu, h, off);
        if (lane >= off && !h) { x = px; tc = pt; h = ph; }
    }

    float ex = __shfl_up_sync(0xffffffffu, x, 1);
    float et = __shfl_up_sync(0xffffffffu, tc, 1);
    int   eh = __shfl_up_sync(0xffffffffu, h, 1);
    if (lane == 0 || !eh) { ex = 0.f; et = seed_t; }

    float sx = ex, stt = et;
#pragma unroll
    for (int j = 0; j < 4; j++) {
        int rc = cbase + j;
        int c = dir ? (CC - 1 - rc) : rc;
        outp[(b * CC + c) * DD + d] = make_float2(sx, stt);
        if (a[j].z != 0.f) { sx = a[j].x; stt = a[j].y; }
    }
}

// ---------------------------------------------------------------------------
// Pass C: fixup of head/tail rows. One thread per (chunk, channel); repairs
// the rows with no in-chunk observation on one side using the incoming
// states + in-chunk aggregates, re-reading only t for those rows.
// ---------------------------------------------------------------------------
__global__ __launch_bounds__(256) void passC(const float* __restrict__ t,
                                             float* __restrict__ out) {
    int id = blockIdx.x * 256 + threadIdx.x;   // [0, NCH*DD)
    int chunk = id >> 7, d = id & 127;
    int row0 = chunk * CHUNK;                  // global row (CC*CHUNK == TT)

    const unsigned char* gh = (const unsigned char*)g_head4;
    const unsigned char* gt = (const unsigned char*)g_tail4;
    int head = gh[id];
    int tail = gt[id];

    if (head > 0) {
        float2 pre = g_pre[id];
        float4 bw  = g_bwd[id];
        float xn, tn;
        if (bw.z != 0.f) { xn = bw.x; tn = bw.y; }
        else { float2 sf = g_suf[id]; xn = sf.x; tn = sf.y; }
        float xl = pre.x, tl = pre.y;
        float denom = tn - tl;
        float inv = (denom != 0.f) ? __fdividef(1.f, denom) : 0.f;
        for (int i = 0; i < head; i++) {
            float tt = t[(row0 + i) * DD + d];
            out[(row0 + i) * DD + d] = fmaf(xl, tn - tt, xn * (tt - tl)) * inv;
        }
    }
    if (tail > 0) {
        float4 fw = g_fwd[id];
        float2 sf = g_suf[id];
        float xl = fw.x, tl = fw.y;
        float xn = sf.x, tn = sf.y;
        float denom = tn - tl;
        float inv = (denom != 0.f) ? __fdividef(1.f, denom) : 0.f;
        for (int i = CHUNK - tail; i < CHUNK; i++) {
            float tt = t[(row0 + i) * DD + d];
            out[(row0 + i) * DD + d] = fmaf(xl, tn - tt, xn * (tt - tl)) * inv;
        }
    }
}

// ---------------------------------------------------------------------------
extern "C" void kernel_launch(void* const* d_in, const int* in_sizes, int n_in,
                              void* d_out, int out_size) {
    const float4* v4 = (const float4*)d_in[0];
    const float4* t4 = (const float4*)d_in[1];
    const int4*   m4 = (const int4*)d_in[2];
    const float*  t  = (const float*)d_in[1];
    float4* out4 = (float4*)d_out;
    float*  out  = (float*)d_out;

    passA<<<NCH, 256>>>(v4, t4, m4, out4);
    passB<<<(2 * BB * DD * 32) / 256, 256>>>(t);
    passC<<<(NCH * DD) / 256, 256>>>(t, out);
}